// round 15
// baseline (speedup 1.0000x reference)
#include <cuda_runtime.h>
#include <cuda_fp16.h>

#define SEQ    256
#define BATCH  32
#define IDIM   256
#define HDIM   512
#define VOCABN 10000
#define SB     (SEQ*BATCH)      /* 8192 */
#define CHUNK  32
#define NCHUNK (SEQ/CHUNK)      /* 8 */
#define MC     (CHUNK*BATCH)    /* 1024 */

#define KSTR   72               /* padded smem k-stride (fp16 elems), 144B */
#define A_EL   (128*KSTR)       /* 9216 */
#define B_EL   (64*KSTR)        /* 4608 */

/* gemm_tn2 (P/Y): m-side single + weight hi/lo (2-pass) */
#define N_STAGE_EL (A_EL + 2*B_EL)      /* 18432 */
#define N_SMEM     (2*N_STAGE_EL*2)     /* 73728 */

/* gemm_T2: m-side single + A single (1-pass) */
#define T_STAGE_EL (A_EL + B_EL)        /* 13824 */
#define T_SMEM     (2*T_STAGE_EL*2)     /* 55296 */

typedef unsigned int u32;

// ---------------- static device scratch ----------------
__device__ __half  g_T0[(size_t)MC * HDIM * HDIM];     // 512 MB, parity 0
__device__ __half  g_T1[(size_t)MC * HDIM * HDIM];     // 512 MB, parity 1
__device__ __half  g_Ah[(size_t)HDIM * IDIM * HDIM];   // A (single fp16)
__device__ __half  g_Wh[(size_t)VOCABN * HDIM];
__device__ __half  g_Wl[(size_t)VOCABN * HDIM];
__device__ __half  g_Uh[(size_t)HDIM * IDIM];
__device__ __half  g_Ul[(size_t)HDIM * IDIM];
__device__ __half  g_X [(size_t)SB * IDIM];            // X single fp16
__device__ __half  g_H [(size_t)SB * HDIM];            // H single fp16
__device__ float   g_P [(size_t)SB * HDIM];

// ---------------- ptx helpers ----------------
__device__ __forceinline__ void mmaf16(float c[4], const u32 a[4], const u32 b[2]) {
    asm volatile(
        "mma.sync.aligned.m16n8k16.row.col.f32.f16.f16.f32 "
        "{%0,%1,%2,%3}, {%4,%5,%6,%7}, {%8,%9}, {%0,%1,%2,%3};\n"
        : "+f"(c[0]), "+f"(c[1]), "+f"(c[2]), "+f"(c[3])
        : "r"(a[0]), "r"(a[1]), "r"(a[2]), "r"(a[3]), "r"(b[0]), "r"(b[1]));
}
__device__ __forceinline__ u32 smem_u32(const void* p) {
    return (u32)__cvta_generic_to_shared(p);
}
__device__ __forceinline__ void cpa16(u32 dst, const void* src, int sz) {
    asm volatile("cp.async.cg.shared.global [%0], [%1], 16, %2;\n"
                 :: "r"(dst), "l"(src), "r"(sz));
}
__device__ __forceinline__ void cpcommit() { asm volatile("cp.async.commit_group;\n"); }
template<int N> __device__ __forceinline__ void cpwait() {
    asm volatile("cp.async.wait_group %0;\n" :: "n"(N));
}
__device__ __forceinline__ void ldsm4(u32& r0, u32& r1, u32& r2, u32& r3, u32 a) {
    asm volatile("ldmatrix.sync.aligned.m8n8.x4.shared.b16 {%0,%1,%2,%3}, [%4];\n"
                 : "=r"(r0), "=r"(r1), "=r"(r2), "=r"(r3) : "r"(a));
}
__device__ __forceinline__ void ldsm4t(u32& r0, u32& r1, u32& r2, u32& r3, u32 a) {
    asm volatile("ldmatrix.sync.aligned.m8n8.x4.trans.shared.b16 {%0,%1,%2,%3}, [%4];\n"
                 : "=r"(r0), "=r"(r1), "=r"(r2), "=r"(r3) : "r"(a));
}

// ---------------- convert / split / embed ----------------
struct __align__(8) Hf4 { __half a, b, c, d; };

__global__ void cvt_kernel(const float4* __restrict__ src, Hf4* __restrict__ dst, int n4) {
    int i = blockIdx.x * blockDim.x + threadIdx.x;
    if (i >= n4) return;
    float4 v = src[i];
    Hf4 h;
    h.a = __float2half_rn(v.x); h.b = __float2half_rn(v.y);
    h.c = __float2half_rn(v.z); h.d = __float2half_rn(v.w);
    dst[i] = h;
}

__global__ void split_kernel(const float4* __restrict__ src,
                             Hf4* __restrict__ hi, Hf4* __restrict__ lo, int n4) {
    int i = blockIdx.x * blockDim.x + threadIdx.x;
    if (i >= n4) return;
    float4 v = src[i];
    Hf4 h, l;
    h.a = __float2half_rn(v.x); l.a = __float2half_rn(v.x - __half2float(h.a));
    h.b = __float2half_rn(v.y); l.b = __float2half_rn(v.y - __half2float(h.b));
    h.c = __float2half_rn(v.z); l.c = __float2half_rn(v.z - __half2float(h.c));
    h.d = __float2half_rn(v.w); l.d = __float2half_rn(v.w - __half2float(h.d));
    hi[i] = h; lo[i] = l;
}

__global__ void embed_kernel(const int* __restrict__ tok, const float* __restrict__ E,
                             __half* __restrict__ X) {
    int sb = blockIdx.x;
    int i  = threadIdx.x;
    X[(size_t)sb * IDIM + i] = __float2half_rn(E[(size_t)tok[sb] * IDIM + i]);
}

// =======================================================================
// T GEMM (1-pass fp16, fp16 output): T[mloc][j][n] = sum_i X*A + V
// BM=128 BN=64 BK=64, 2-stage cp.async, ldmatrix(.trans).
// grid (MC/128, HDIM/64, HDIM)
// =======================================================================
__global__ __launch_bounds__(256) void gemm_T2(
    const float* __restrict__ Vw, __half* __restrict__ T, int chunk)
{
    extern __shared__ __half sm[];
    const int tid = threadIdx.x, lane = tid & 31, w = tid >> 5;
    const int grp = lane >> 2, qp2 = (lane & 3) * 2;
    const int wm0 = (w & 3) * 32, wn0 = (w >> 2) * 32;
    const int j = blockIdx.z, mBase = blockIdx.x * 128, nBase = blockIdx.y * 64;
    const int mG = chunk * MC + mBase;

    float acc[2][4][4];
#pragma unroll
    for (int a = 0; a < 2; a++)
#pragma unroll
        for (int b = 0; b < 4; b++)
#pragma unroll
            for (int c = 0; c < 4; c++) acc[a][b][c] = 0.f;

#define PREFETCH_T(kc_) do {                                                   \
    int st_ = (kc_) & 1;                                                       \
    int kB_ = (kc_) * 64;                                                      \
    __half* Xs_ = sm + st_ * T_STAGE_EL;                                       \
    __half* Bh_ = Xs_ + A_EL;                                                  \
    _Pragma("unroll")                                                          \
    for (int q = 0; q < 4; q++) {                                              \
        int id = q * 256 + tid;                                                \
        int row = id >> 3, ks = (id & 7) * 8;                                  \
        size_t g = (size_t)(mG + row) * IDIM + kB_ + ks;                       \
        cpa16(smem_u32(Xs_ + row * KSTR + ks), g_X + g, 16);                   \
    }                                                                          \
    _Pragma("unroll")                                                          \
    for (int q = 0; q < 2; q++) {                                              \
        int id = q * 256 + tid;                                                \
        int kr = id >> 3, ns = (id & 7) * 8;                                   \
        size_t g = ((size_t)j * IDIM + kB_ + kr) * HDIM + nBase + ns;          \
        cpa16(smem_u32(Bh_ + kr * KSTR + ns), g_Ah + g, 16);                   \
    } } while (0)

    PREFETCH_T(0); cpcommit();

    const int r8 = lane & 7, kh = (lane >> 3) & 1, nh = lane >> 4;

    for (int kc = 0; kc < 4; kc++) {
        if (kc < 3) { PREFETCH_T(kc + 1); cpcommit(); cpwait<1>(); }
        else        { cpwait<0>(); }
        __syncthreads();
        int st = kc & 1;
        __half* Xs_ = sm + st * T_STAGE_EL;
        u32 aAd  = smem_u32(Xs_ + (wm0 + (lane & 15)) * KSTR + (lane >> 4) * 8);
        u32 bAdH = smem_u32(Xs_ + A_EL + (kh * 8 + r8) * KSTR + wn0 + nh * 8);
#pragma unroll
        for (int ks = 0; ks < 4; ks++) {
            u32 aF[2][4], bH[4][2];
            ldsm4(aF[0][0], aF[0][1], aF[0][2], aF[0][3], aAd + ks * 32);
            ldsm4(aF[1][0], aF[1][1], aF[1][2], aF[1][3], aAd + 2304 + ks * 32);
            ldsm4t(bH[0][0], bH[0][1], bH[1][0], bH[1][1], bAdH + ks * 2304);
            ldsm4t(bH[2][0], bH[2][1], bH[3][0], bH[3][1], bAdH + 32 + ks * 2304);
#pragma unroll
            for (int mt = 0; mt < 2; mt++)
#pragma unroll
                for (int nt = 0; nt < 4; nt++)
                    mmaf16(acc[mt][nt], aF[mt], bH[nt]);
        }
        __syncthreads();
    }
#undef PREFETCH_T

#pragma unroll
    for (int mt = 0; mt < 2; mt++)
#pragma unroll
        for (int nt = 0; nt < 4; nt++) {
            int r  = mBase + wm0 + mt * 16 + grp;
            int cc = nBase + wn0 + nt * 8 + qp2;
            float2 v2 = *(const float2*)&Vw[(size_t)j * HDIM + cc];
            size_t base = ((size_t)r * HDIM + j) * HDIM + cc;
            *(__half2*)&T[base] =
                __floats2half2_rn(acc[mt][nt][0] + v2.x, acc[mt][nt][1] + v2.y);
            *(__half2*)&T[base + (size_t)8 * HDIM * HDIM] =
                __floats2half2_rn(acc[mt][nt][2] + v2.x, acc[mt][nt][3] + v2.y);
        }
}

// =======================================================================
// TN GEMM (2-pass fp16): C[m][n] = sum_k A[m][k]*B[n][k] + bias[n]
// =======================================================================
__global__ __launch_bounds__(256) void gemm_tn2(
    const __half* __restrict__ Ap,
    const __half* __restrict__ Bhp, const __half* __restrict__ Blp,
    const float* __restrict__ bias, float* __restrict__ C, int N, int K)
{
    extern __shared__ __half sm[];
    const int tid = threadIdx.x, lane = tid & 31, w = tid >> 5;
    const int grp = lane >> 2, qp2 = (lane & 3) * 2;
    const int wm0 = (w & 3) * 32, wn0 = (w >> 2) * 32;
    const int mBase = blockIdx.x * 128, nBase = blockIdx.y * 64;
    const int KC = K >> 6;

    float acc[2][4][4];
#pragma unroll
    for (int a = 0; a < 2; a++)
#pragma unroll
        for (int b = 0; b < 4; b++)
#pragma unroll
            for (int c = 0; c < 4; c++) acc[a][b][c] = 0.f;

#define PREFETCH_N(kc_) do {                                                   \
    int st_ = (kc_) & 1;                                                       \
    int kB_ = (kc_) * 64;                                                      \
    __half* As_ = sm + st_ * N_STAGE_EL;                                       \
    __half* Bh_ = As_ + A_EL;                                                  \
    __half* Bl_ = Bh_ + B_EL;                                                  \
    _Pragma("unroll")                                                          \
    for (int q = 0; q < 4; q++) {                                              \
        int id = q * 256 + tid;                                                \
        int row = id >> 3, ks = (id & 7) * 8;                                  \
        size_t g = (size_t)(mBase + row) * K + kB_ + ks;                       \
        cpa16(smem_u32(As_ + row * KSTR + ks), Ap + g, 16);                    \
    }                                                                          \
    _Pragma("unroll")                                                          \
    for (int q = 0; q < 2; q++) {                                              \
        int id = q * 256 + tid;                                                \
        int nr = id >> 3, ks = (id & 7) * 8;                                   \
        int gn = nBase + nr;                                                   \
        int ok = gn < N;                                                       \
        int gc = ok ? gn : (N - 1);                                            \
        size_t g = (size_t)gc * K + kB_ + ks;                                  \
        cpa16(smem_u32(Bh_ + nr * KSTR + ks), Bhp + g, ok ? 16 : 0);           \
        cpa16(smem_u32(Bl_ + nr * KSTR + ks), Blp + g, ok ? 16 : 0);           \
    } } while (0)

    PREFETCH_N(0); cpcommit();

    const int r8 = lane & 7, kh = (lane >> 3) & 1, nh = lane >> 4;

    for (int kc = 0; kc < KC; kc++) {
        if (kc < KC - 1) { PREFETCH_N(kc + 1); cpcommit(); cpwait<1>(); }
        else             { cpwait<0>(); }
        __syncthreads();
        int st = kc & 1;
        __half* As_ = sm + st * N_STAGE_EL;
        u32 aAd  = smem_u32(As_ + (wm0 + (lane & 15)) * KSTR + (lane >> 4) * 8);
        u32 bAdH = smem_u32(As_ + A_EL + (wn0 + nh * 8 + r8) * KSTR + kh * 8);
        u32 bAdL = bAdH + B_EL * 2;
#pragma unroll
        for (int ks = 0; ks < 4; ks++) {
            u32 aF[2][4], bH[4][2], bL[4][2];
            ldsm4(aF[0][0], aF[0][1], aF[0][2], aF[0][3], aAd + ks * 32);
            ldsm4(aF[1][0], aF[1][1], aF[1][2], aF[1][3], aAd + 2304 + ks * 32);
            ldsm4(bH[0][0], bH[0][1], bH[1][0], bH[1][1], bAdH + ks * 32);
            ldsm4(bH[2][0], bH[2][1], bH[3][0], bH[3][1], bAdH + 2304 + ks * 32);
            ldsm4(bL[0][0], bL[0][1], bL[1][0], bL[1][1], bAdL + ks * 32);
            ldsm4(bL[2][0], bL[2][1], bL[3][0], bL[3][1], bAdL + 2304 + ks * 32);
#pragma unroll
            for (int mt = 0; mt < 2; mt++)
#pragma unroll
                for (int nt = 0; nt < 4; nt++)
                    mmaf16(acc[mt][nt], aF[mt], bH[nt]);
#pragma unroll
            for (int mt = 0; mt < 2; mt++)
#pragma unroll
                for (int nt = 0; nt < 4; nt++)
                    mmaf16(acc[mt][nt], aF[mt], bL[nt]);
        }
        __syncthreads();
    }
#undef PREFETCH_N

#pragma unroll
    for (int mt = 0; mt < 2; mt++)
#pragma unroll
        for (int nt = 0; nt < 4; nt++) {
            int r0 = mBase + wm0 + mt * 16 + grp;
            int cc = nBase + wn0 + nt * 8 + qp2;
            if (cc < N) {
                float b0 = bias[cc], b1 = bias[cc + 1];
                *(float2*)&C[(size_t)r0 * N + cc] =
                    make_float2(acc[mt][nt][0] + b0, acc[mt][nt][1] + b1);
                *(float2*)&C[(size_t)(r0 + 8) * N + cc] =
                    make_float2(acc[mt][nt][2] + b0, acc[mt][nt][3] + b1);
            }
        }
}

// =======================================================================
// Fused recurrence, one chunk, NO inter-block dependency:
// grid 32 (one block per batch row), h state ping-pongs in smem.
// h_s = relu( T'[m_s] . h_{s-1} + P[m_s] ); T fp16 [mloc][j][k].
// =======================================================================
__global__ __launch_bounds__(256) void recur_chunk32(
    const __half* __restrict__ T, int chunk,
    float* __restrict__ Hfull, __half* __restrict__ Hh)
{
    const int tid = threadIdx.x, lane = tid & 31, w = tid >> 5;
    const int bb = blockIdx.x;
    __shared__ float hs[2][HDIM];
    int p = 0;

    if (chunk == 0) {
        for (int k = tid; k < HDIM; k += 256) hs[0][k] = 0.f;
    } else {
        const float* hp = Hfull + ((size_t)(chunk * CHUNK - 1) * BATCH + bb) * HDIM;
        for (int k = tid; k < HDIM; k += 256) hs[0][k] = hp[k];
    }
    __syncthreads();

    for (int t = 0; t < CHUNK; t++) {
        const int s = chunk * CHUNK + t;
        const int mloc = t * BATCH + bb;
        const int m    = s * BATCH + bb;
        const float* hp = hs[p];
        // warp w owns j in [w*64, w*64+64)
#pragma unroll 2
        for (int jq = 0; jq < 64; jq++) {
            int j = w * 64 + jq;
            const uint4* row = (const uint4*)(T + ((size_t)mloc * HDIM + j) * HDIM);
            float a = 0.f;
#pragma unroll
            for (int q = 0; q < 2; q++) {
                uint4 v = row[lane + q * 32];
                const __half2* h2 = (const __half2*)&v;
                int k = (lane + q * 32) * 8;
#pragma unroll
                for (int u = 0; u < 4; u++) {
                    float2 f = __half22float2(h2[u]);
                    a += f.x * hp[k + 2 * u] + f.y * hp[k + 2 * u + 1];
                }
            }
#pragma unroll
            for (int off = 16; off; off >>= 1) a += __shfl_xor_sync(~0u, a, off);
            if (lane == 0) {
                float pre = a + g_P[(size_t)m * HDIM + j];
                float h = pre > 0.f ? pre : 0.f;
                hs[1 - p][j] = h;
                Hfull[(size_t)m * HDIM + j] = h;
                Hh[(size_t)m * HDIM + j] = __float2half_rn(h);
            }
        }
        __syncthreads();
        p ^= 1;
    }
}

// ---------------- host ----------------
extern "C" void kernel_launch(void* const* d_in, const int* in_sizes, int n_in,
                              void* d_out, int out_size) {
    const int*   tok = (const int*)  d_in[0];
    const float* E   = (const float*)d_in[1];
    const float* A   = (const float*)d_in[2];
    const float* U   = (const float*)d_in[3];
    const float* V   = (const float*)d_in[4];
    const float* bv  = (const float*)d_in[5];
    const float* W   = (const float*)d_in[6];
    const float* cv  = (const float*)d_in[7];

    float* y_out = (float*)d_out;                              // [SB][VOCAB]
    float* h_out = (float*)d_out + (size_t)SB * VOCABN;        // [SB][H]

    void *pT0, *pT1, *pAh, *pWh, *pWl, *pUh, *pUl, *pX, *pH, *pP;
    cudaGetSymbolAddress(&pT0, g_T0); cudaGetSymbolAddress(&pT1, g_T1);
    cudaGetSymbolAddress(&pAh, g_Ah);
    cudaGetSymbolAddress(&pWh, g_Wh); cudaGetSymbolAddress(&pWl, g_Wl);
    cudaGetSymbolAddress(&pUh, g_Uh); cudaGetSymbolAddress(&pUl, g_Ul);
    cudaGetSymbolAddress(&pX,  g_X);  cudaGetSymbolAddress(&pH,  g_H);
    cudaGetSymbolAddress(&pP,  g_P);
    __half* bufT[2] = { (__half*)pT0, (__half*)pT1 };

    cudaFuncSetAttribute(gemm_T2, cudaFuncAttributeMaxDynamicSharedMemorySize, T_SMEM);
    cudaFuncSetAttribute(gemm_tn2, cudaFuncAttributeMaxDynamicSharedMemorySize, N_SMEM);

    cudaStream_t s2;
    cudaStreamCreateWithFlags(&s2, cudaStreamNonBlocking);
    cudaEvent_t evG[NCHUNK], evR[NCHUNK];
    for (int c = 0; c < NCHUNK; c++) {
        cudaEventCreateWithFlags(&evG[c], cudaEventDisableTiming);
        cudaEventCreateWithFlags(&evR[c], cudaEventDisableTiming);
    }

    // 1) A -> single fp16; W/U -> fp16 hi/lo splits
    {
        int n4 = (HDIM * IDIM * HDIM) / 4;
        cvt_kernel<<<(n4 + 255) / 256, 256>>>((const float4*)A, (Hf4*)pAh, n4);
        n4 = (VOCABN * HDIM) / 4;
        split_kernel<<<(n4 + 255) / 256, 256>>>((const float4*)W, (Hf4*)pWh, (Hf4*)pWl, n4);
        n4 = (HDIM * IDIM) / 4;
        split_kernel<<<(n4 + 255) / 256, 256>>>((const float4*)U, (Hf4*)pUh, (Hf4*)pUl, n4);
    }
    // 2) embedding gather (single fp16)
    embed_kernel<<<SB, IDIM>>>(tok, E, (__half*)pX);

    // 3) P = X @ U^T + b
    gemm_tn2<<<dim3(SB / 128, HDIM / 64), 256, N_SMEM>>>(
        (const __half*)pX, (const __half*)pUh, (const __half*)pUl,
        bv, (float*)pP, HDIM, IDIM);

    // 4) pipeline: gemm_T(c) on stream 0; fused recur(c) on s2 (32 blocks,
    //    no inter-block dep -> safe to overlap gemm_T(c+1)).
    //    WAR guard: gemm_T(c) (writing bufT[c&1]) waits recur(c-2).
    for (int c = 0; c < NCHUNK; c++) {
        if (c >= 2) cudaStreamWaitEvent(0, evR[c - 2], 0);
        gemm_T2<<<dim3(MC / 128, HDIM / 64, HDIM), 256, T_SMEM>>>(V, bufT[c & 1], c);
        cudaEventRecord(evG[c], 0);
        cudaStreamWaitEvent(s2, evG[c], 0);
        recur_chunk32<<<32, 256, 0, s2>>>(bufT[c & 1], c, h_out, (__half*)pH);
        cudaEventRecord(evR[c], s2);
    }
    cudaStreamWaitEvent(0, evR[NCHUNK - 1], 0);

    // 5) Y = H @ W^T + c
    gemm_tn2<<<dim3(SB / 128, (VOCABN + 63) / 64), 256, N_SMEM>>>(
        (const __half*)pH, (const __half*)pWh, (const __half*)pWl,
        cv, y_out, VOCABN, HDIM);
}

// round 16
// speedup vs baseline: 1.7336x; 1.7336x over previous
#include <cuda_runtime.h>
#include <cuda_fp16.h>

#define SEQ    256
#define BATCH  32
#define IDIM   256
#define HDIM   512
#define VOCABN 10000
#define SB     (SEQ*BATCH)      /* 8192 */
#define CHUNK  32
#define NCHUNK (SEQ/CHUNK)      /* 8 */
#define MC     (CHUNK*BATCH)    /* 1024 */

#define KSTR   72               /* padded smem k-stride (fp16 elems), 144B */
#define A_EL   (128*KSTR)       /* 9216 */
#define B_EL   (64*KSTR)        /* 4608 */

/* gemm_tn2 (P/Y): m-side single + weight hi/lo (2-pass) */
#define N_STAGE_EL (A_EL + 2*B_EL)      /* 18432 */
#define N_SMEM     (2*N_STAGE_EL*2)     /* 73728 */

/* gemm_T2: m-side single + A single (1-pass) */
#define T_STAGE_EL (A_EL + B_EL)        /* 13824 */
#define T_SMEM     (2*T_STAGE_EL*2)     /* 55296 */

typedef unsigned int u32;

// ---------------- static device scratch ----------------
__device__ __half  g_T0[(size_t)MC * HDIM * HDIM];     // 512 MB, parity 0
__device__ __half  g_T1[(size_t)MC * HDIM * HDIM];     // 512 MB, parity 1
__device__ __half  g_Ah[(size_t)HDIM * IDIM * HDIM];   // A (single fp16)
__device__ __half  g_Wh[(size_t)VOCABN * HDIM];
__device__ __half  g_Wl[(size_t)VOCABN * HDIM];
__device__ __half  g_Uh[(size_t)HDIM * IDIM];
__device__ __half  g_Ul[(size_t)HDIM * IDIM];
__device__ __half  g_X [(size_t)SB * IDIM];            // X single fp16
__device__ __half  g_H [(size_t)SB * HDIM];            // H single fp16
__device__ float   g_P [(size_t)SB * HDIM];

// ---------------- ptx helpers ----------------
__device__ __forceinline__ void mmaf16(float c[4], const u32 a[4], const u32 b[2]) {
    asm volatile(
        "mma.sync.aligned.m16n8k16.row.col.f32.f16.f16.f32 "
        "{%0,%1,%2,%3}, {%4,%5,%6,%7}, {%8,%9}, {%0,%1,%2,%3};\n"
        : "+f"(c[0]), "+f"(c[1]), "+f"(c[2]), "+f"(c[3])
        : "r"(a[0]), "r"(a[1]), "r"(a[2]), "r"(a[3]), "r"(b[0]), "r"(b[1]));
}
__device__ __forceinline__ u32 smem_u32(const void* p) {
    return (u32)__cvta_generic_to_shared(p);
}
__device__ __forceinline__ void cpa16(u32 dst, const void* src, int sz) {
    asm volatile("cp.async.cg.shared.global [%0], [%1], 16, %2;\n"
                 :: "r"(dst), "l"(src), "r"(sz));
}
__device__ __forceinline__ void cpcommit() { asm volatile("cp.async.commit_group;\n"); }
template<int N> __device__ __forceinline__ void cpwait() {
    asm volatile("cp.async.wait_group %0;\n" :: "n"(N));
}
__device__ __forceinline__ void ldsm4(u32& r0, u32& r1, u32& r2, u32& r3, u32 a) {
    asm volatile("ldmatrix.sync.aligned.m8n8.x4.shared.b16 {%0,%1,%2,%3}, [%4];\n"
                 : "=r"(r0), "=r"(r1), "=r"(r2), "=r"(r3) : "r"(a));
}
__device__ __forceinline__ void ldsm4t(u32& r0, u32& r1, u32& r2, u32& r3, u32 a) {
    asm volatile("ldmatrix.sync.aligned.m8n8.x4.trans.shared.b16 {%0,%1,%2,%3}, [%4];\n"
                 : "=r"(r0), "=r"(r1), "=r"(r2), "=r"(r3) : "r"(a));
}

// ---------------- convert / split / embed ----------------
struct __align__(8) Hf4 { __half a, b, c, d; };

__global__ void cvt_kernel(const float4* __restrict__ src, Hf4* __restrict__ dst, int n4) {
    int i = blockIdx.x * blockDim.x + threadIdx.x;
    if (i >= n4) return;
    float4 v = src[i];
    Hf4 h;
    h.a = __float2half_rn(v.x); h.b = __float2half_rn(v.y);
    h.c = __float2half_rn(v.z); h.d = __float2half_rn(v.w);
    dst[i] = h;
}

__global__ void split_kernel(const float4* __restrict__ src,
                             Hf4* __restrict__ hi, Hf4* __restrict__ lo, int n4) {
    int i = blockIdx.x * blockDim.x + threadIdx.x;
    if (i >= n4) return;
    float4 v = src[i];
    Hf4 h, l;
    h.a = __float2half_rn(v.x); l.a = __float2half_rn(v.x - __half2float(h.a));
    h.b = __float2half_rn(v.y); l.b = __float2half_rn(v.y - __half2float(h.b));
    h.c = __float2half_rn(v.z); l.c = __float2half_rn(v.z - __half2float(h.c));
    h.d = __float2half_rn(v.w); l.d = __float2half_rn(v.w - __half2float(h.d));
    hi[i] = h; lo[i] = l;
}

__global__ void embed_kernel(const int* __restrict__ tok, const float* __restrict__ E,
                             __half* __restrict__ X) {
    int sb = blockIdx.x;
    int i  = threadIdx.x;
    X[(size_t)sb * IDIM + i] = __float2half_rn(E[(size_t)tok[sb] * IDIM + i]);
}

// =======================================================================
// T GEMM (1-pass fp16, fp16 output): T[mloc][j][n] = sum_i X*A + V
// BM=128 BN=64 BK=64, 2-stage cp.async, ldmatrix(.trans).
// grid (MC/128, HDIM/64, HDIM)
// =======================================================================
__global__ __launch_bounds__(256) void gemm_T2(
    const float* __restrict__ Vw, __half* __restrict__ T, int chunk)
{
    extern __shared__ __half sm[];
    const int tid = threadIdx.x, lane = tid & 31, w = tid >> 5;
    const int grp = lane >> 2, qp2 = (lane & 3) * 2;
    const int wm0 = (w & 3) * 32, wn0 = (w >> 2) * 32;
    const int j = blockIdx.z, mBase = blockIdx.x * 128, nBase = blockIdx.y * 64;
    const int mG = chunk * MC + mBase;

    float acc[2][4][4];
#pragma unroll
    for (int a = 0; a < 2; a++)
#pragma unroll
        for (int b = 0; b < 4; b++)
#pragma unroll
            for (int c = 0; c < 4; c++) acc[a][b][c] = 0.f;

#define PREFETCH_T(kc_) do {                                                   \
    int st_ = (kc_) & 1;                                                       \
    int kB_ = (kc_) * 64;                                                      \
    __half* Xs_ = sm + st_ * T_STAGE_EL;                                       \
    __half* Bh_ = Xs_ + A_EL;                                                  \
    _Pragma("unroll")                                                          \
    for (int q = 0; q < 4; q++) {                                              \
        int id = q * 256 + tid;                                                \
        int row = id >> 3, ks = (id & 7) * 8;                                  \
        size_t g = (size_t)(mG + row) * IDIM + kB_ + ks;                       \
        cpa16(smem_u32(Xs_ + row * KSTR + ks), g_X + g, 16);                   \
    }                                                                          \
    _Pragma("unroll")                                                          \
    for (int q = 0; q < 2; q++) {                                              \
        int id = q * 256 + tid;                                                \
        int kr = id >> 3, ns = (id & 7) * 8;                                   \
        size_t g = ((size_t)j * IDIM + kB_ + kr) * HDIM + nBase + ns;          \
        cpa16(smem_u32(Bh_ + kr * KSTR + ns), g_Ah + g, 16);                   \
    } } while (0)

    PREFETCH_T(0); cpcommit();

    const int r8 = lane & 7, kh = (lane >> 3) & 1, nh = lane >> 4;

    for (int kc = 0; kc < 4; kc++) {
        if (kc < 3) { PREFETCH_T(kc + 1); cpcommit(); cpwait<1>(); }
        else        { cpwait<0>(); }
        __syncthreads();
        int st = kc & 1;
        __half* Xs_ = sm + st * T_STAGE_EL;
        u32 aAd  = smem_u32(Xs_ + (wm0 + (lane & 15)) * KSTR + (lane >> 4) * 8);
        u32 bAdH = smem_u32(Xs_ + A_EL + (kh * 8 + r8) * KSTR + wn0 + nh * 8);
#pragma unroll
        for (int ks = 0; ks < 4; ks++) {
            u32 aF[2][4], bH[4][2];
            ldsm4(aF[0][0], aF[0][1], aF[0][2], aF[0][3], aAd + ks * 32);
            ldsm4(aF[1][0], aF[1][1], aF[1][2], aF[1][3], aAd + 2304 + ks * 32);
            ldsm4t(bH[0][0], bH[0][1], bH[1][0], bH[1][1], bAdH + ks * 2304);
            ldsm4t(bH[2][0], bH[2][1], bH[3][0], bH[3][1], bAdH + 32 + ks * 2304);
#pragma unroll
            for (int mt = 0; mt < 2; mt++)
#pragma unroll
                for (int nt = 0; nt < 4; nt++)
                    mmaf16(acc[mt][nt], aF[mt], bH[nt]);
        }
        __syncthreads();
    }
#undef PREFETCH_T

#pragma unroll
    for (int mt = 0; mt < 2; mt++)
#pragma unroll
        for (int nt = 0; nt < 4; nt++) {
            int r  = mBase + wm0 + mt * 16 + grp;
            int cc = nBase + wn0 + nt * 8 + qp2;
            float2 v2 = *(const float2*)&Vw[(size_t)j * HDIM + cc];
            size_t base = ((size_t)r * HDIM + j) * HDIM + cc;
            *(__half2*)&T[base] =
                __floats2half2_rn(acc[mt][nt][0] + v2.x, acc[mt][nt][1] + v2.y);
            *(__half2*)&T[base + (size_t)8 * HDIM * HDIM] =
                __floats2half2_rn(acc[mt][nt][2] + v2.x, acc[mt][nt][3] + v2.y);
        }
}

// =======================================================================
// TN GEMM (2-pass fp16): C[m][n] = sum_k A[m][k]*B[n][k] + bias[n]
// =======================================================================
__global__ __launch_bounds__(256) void gemm_tn2(
    const __half* __restrict__ Ap,
    const __half* __restrict__ Bhp, const __half* __restrict__ Blp,
    const float* __restrict__ bias, float* __restrict__ C, int N, int K)
{
    extern __shared__ __half sm[];
    const int tid = threadIdx.x, lane = tid & 31, w = tid >> 5;
    const int grp = lane >> 2, qp2 = (lane & 3) * 2;
    const int wm0 = (w & 3) * 32, wn0 = (w >> 2) * 32;
    const int mBase = blockIdx.x * 128, nBase = blockIdx.y * 64;
    const int KC = K >> 6;

    float acc[2][4][4];
#pragma unroll
    for (int a = 0; a < 2; a++)
#pragma unroll
        for (int b = 0; b < 4; b++)
#pragma unroll
            for (int c = 0; c < 4; c++) acc[a][b][c] = 0.f;

#define PREFETCH_N(kc_) do {                                                   \
    int st_ = (kc_) & 1;                                                       \
    int kB_ = (kc_) * 64;                                                      \
    __half* As_ = sm + st_ * N_STAGE_EL;                                       \
    __half* Bh_ = As_ + A_EL;                                                  \
    __half* Bl_ = Bh_ + B_EL;                                                  \
    _Pragma("unroll")                                                          \
    for (int q = 0; q < 4; q++) {                                              \
        int id = q * 256 + tid;                                                \
        int row = id >> 3, ks = (id & 7) * 8;                                  \
        size_t g = (size_t)(mBase + row) * K + kB_ + ks;                       \
        cpa16(smem_u32(As_ + row * KSTR + ks), Ap + g, 16);                    \
    }                                                                          \
    _Pragma("unroll")                                                          \
    for (int q = 0; q < 2; q++) {                                              \
        int id = q * 256 + tid;                                                \
        int nr = id >> 3, ks = (id & 7) * 8;                                   \
        int gn = nBase + nr;                                                   \
        int ok = gn < N;                                                       \
        int gc = ok ? gn : (N - 1);                                            \
        size_t g = (size_t)gc * K + kB_ + ks;                                  \
        cpa16(smem_u32(Bh_ + nr * KSTR + ks), Bhp + g, ok ? 16 : 0);           \
        cpa16(smem_u32(Bl_ + nr * KSTR + ks), Blp + g, ok ? 16 : 0);           \
    } } while (0)

    PREFETCH_N(0); cpcommit();

    const int r8 = lane & 7, kh = (lane >> 3) & 1, nh = lane >> 4;

    for (int kc = 0; kc < KC; kc++) {
        if (kc < KC - 1) { PREFETCH_N(kc + 1); cpcommit(); cpwait<1>(); }
        else             { cpwait<0>(); }
        __syncthreads();
        int st = kc & 1;
        __half* As_ = sm + st * N_STAGE_EL;
        u32 aAd  = smem_u32(As_ + (wm0 + (lane & 15)) * KSTR + (lane >> 4) * 8);
        u32 bAdH = smem_u32(As_ + A_EL + (wn0 + nh * 8 + r8) * KSTR + kh * 8);
        u32 bAdL = bAdH + B_EL * 2;
#pragma unroll
        for (int ks = 0; ks < 4; ks++) {
            u32 aF[2][4], bH[4][2], bL[4][2];
            ldsm4(aF[0][0], aF[0][1], aF[0][2], aF[0][3], aAd + ks * 32);
            ldsm4(aF[1][0], aF[1][1], aF[1][2], aF[1][3], aAd + 2304 + ks * 32);
            ldsm4(bH[0][0], bH[0][1], bH[1][0], bH[1][1], bAdH + ks * 32);
            ldsm4(bH[2][0], bH[2][1], bH[3][0], bH[3][1], bAdH + 2304 + ks * 32);
            ldsm4(bL[0][0], bL[0][1], bL[1][0], bL[1][1], bAdL + ks * 32);
            ldsm4(bL[2][0], bL[2][1], bL[3][0], bL[3][1], bAdL + 2304 + ks * 32);
#pragma unroll
            for (int mt = 0; mt < 2; mt++)
#pragma unroll
                for (int nt = 0; nt < 4; nt++)
                    mmaf16(acc[mt][nt], aF[mt], bH[nt]);
#pragma unroll
            for (int mt = 0; mt < 2; mt++)
#pragma unroll
                for (int nt = 0; nt < 4; nt++)
                    mmaf16(acc[mt][nt], aF[mt], bL[nt]);
        }
        __syncthreads();
    }
#undef PREFETCH_N

#pragma unroll
    for (int mt = 0; mt < 2; mt++)
#pragma unroll
        for (int nt = 0; nt < 4; nt++) {
            int r0 = mBase + wm0 + mt * 16 + grp;
            int cc = nBase + wn0 + nt * 8 + qp2;
            if (cc < N) {
                float b0 = bias[cc], b1 = bias[cc + 1];
                *(float2*)&C[(size_t)r0 * N + cc] =
                    make_float2(acc[mt][nt][0] + b0, acc[mt][nt][1] + b1);
                *(float2*)&C[(size_t)(r0 + 8) * N + cc] =
                    make_float2(acc[mt][nt][2] + b0, acc[mt][nt][3] + b1);
            }
        }
}

// ------------- recurrence (per-step, 1024 blocks, fp16 T) -------------
// h_s = relu( T'[m_s] . h_{s-1} + P[m_s] );  T fp16 [mloc][j][k]
__global__ __launch_bounds__(256) void recur_step(
    const __half* __restrict__ T, int sLocal, int s,
    float* __restrict__ Hfull, __half* __restrict__ Hh)
{
    const int tid = threadIdx.x, lane = tid & 31, w = tid >> 5;
    const int b = blockIdx.x & 31, jt = blockIdx.x >> 5;
    __shared__ float hs[HDIM];
    if (s > 0) {
        const float* hp = Hfull + ((size_t)(s - 1) * BATCH + b) * HDIM;
        for (int k = tid; k < HDIM; k += 256) hs[k] = hp[k];
    }
    __syncthreads();
    const int mloc = sLocal * BATCH + b;
    const int m    = s * BATCH + b;
#pragma unroll
    for (int jj = 0; jj < 2; jj++) {
        int j = jt * 16 + w * 2 + jj;
        float a = 0.f;
        if (s > 0) {
            const uint4* row = (const uint4*)(T + ((size_t)mloc * HDIM + j) * HDIM);
#pragma unroll
            for (int q = 0; q < 2; q++) {
                uint4 v = row[lane + q * 32];
                const __half2* h2 = (const __half2*)&v;
                int k = (lane + q * 32) * 8;
#pragma unroll
                for (int u = 0; u < 4; u++) {
                    float2 f = __half22float2(h2[u]);
                    a += f.x * hs[k + 2 * u] + f.y * hs[k + 2 * u + 1];
                }
            }
        }
#pragma unroll
        for (int off = 16; off; off >>= 1) a += __shfl_xor_sync(~0u, a, off);
        if (lane == 0) {
            float pre = a + g_P[(size_t)m * HDIM + j];
            float h = pre > 0.f ? pre : 0.f;
            Hfull[(size_t)m * HDIM + j] = h;
            Hh[(size_t)m * HDIM + j] = __float2half_rn(h);
        }
    }
}

// ---------------- host ----------------
extern "C" void kernel_launch(void* const* d_in, const int* in_sizes, int n_in,
                              void* d_out, int out_size) {
    const int*   tok = (const int*)  d_in[0];
    const float* E   = (const float*)d_in[1];
    const float* A   = (const float*)d_in[2];
    const float* U   = (const float*)d_in[3];
    const float* V   = (const float*)d_in[4];
    const float* bv  = (const float*)d_in[5];
    const float* W   = (const float*)d_in[6];
    const float* cv  = (const float*)d_in[7];

    float* y_out = (float*)d_out;                              // [SB][VOCAB]
    float* h_out = (float*)d_out + (size_t)SB * VOCABN;        // [SB][H]

    void *pT0, *pT1, *pAh, *pWh, *pWl, *pUh, *pUl, *pX, *pH, *pP;
    cudaGetSymbolAddress(&pT0, g_T0); cudaGetSymbolAddress(&pT1, g_T1);
    cudaGetSymbolAddress(&pAh, g_Ah);
    cudaGetSymbolAddress(&pWh, g_Wh); cudaGetSymbolAddress(&pWl, g_Wl);
    cudaGetSymbolAddress(&pUh, g_Uh); cudaGetSymbolAddress(&pUl, g_Ul);
    cudaGetSymbolAddress(&pX,  g_X);  cudaGetSymbolAddress(&pH,  g_H);
    cudaGetSymbolAddress(&pP,  g_P);
    __half* bufT[2] = { (__half*)pT0, (__half*)pT1 };

    cudaFuncSetAttribute(gemm_T2, cudaFuncAttributeMaxDynamicSharedMemorySize, T_SMEM);
    cudaFuncSetAttribute(gemm_tn2, cudaFuncAttributeMaxDynamicSharedMemorySize, N_SMEM);

    cudaStream_t s2;
    cudaStreamCreateWithFlags(&s2, cudaStreamNonBlocking);
    cudaEvent_t evG[NCHUNK], evR[NCHUNK];
    for (int c = 0; c < NCHUNK; c++) {
        cudaEventCreateWithFlags(&evG[c], cudaEventDisableTiming);
        cudaEventCreateWithFlags(&evR[c], cudaEventDisableTiming);
    }

    // 1) A -> single fp16; W/U -> fp16 hi/lo splits
    {
        int n4 = (HDIM * IDIM * HDIM) / 4;
        cvt_kernel<<<(n4 + 255) / 256, 256>>>((const float4*)A, (Hf4*)pAh, n4);
        n4 = (VOCABN * HDIM) / 4;
        split_kernel<<<(n4 + 255) / 256, 256>>>((const float4*)W, (Hf4*)pWh, (Hf4*)pWl, n4);
        n4 = (HDIM * IDIM) / 4;
        split_kernel<<<(n4 + 255) / 256, 256>>>((const float4*)U, (Hf4*)pUh, (Hf4*)pUl, n4);
    }
    // 2) embedding gather (single fp16)
    embed_kernel<<<SB, IDIM>>>(tok, E, (__half*)pX);

    // 3) P = X @ U^T + b
    gemm_tn2<<<dim3(SB / 128, HDIM / 64), 256, N_SMEM>>>(
        (const __half*)pX, (const __half*)pUh, (const __half*)pUl,
        bv, (float*)pP, HDIM, IDIM);

    // 4) pipeline: gemm_T(c) on stream 0; per-step recur chain on s2.
    //    WAR guard: gemm_T(c) (writing bufT[c&1]) waits recur(c-2).
    for (int c = 0; c < NCHUNK; c++) {
        if (c >= 2) cudaStreamWaitEvent(0, evR[c - 2], 0);
        gemm_T2<<<dim3(MC / 128, HDIM / 64, HDIM), 256, T_SMEM>>>(V, bufT[c & 1], c);
        cudaEventRecord(evG[c], 0);
        cudaStreamWaitEvent(s2, evG[c], 0);
        for (int t = 0; t < CHUNK; t++) {
            int s = c * CHUNK + t;
            recur_step<<<1024, 256, 0, s2>>>(bufT[c & 1], t, s, h_out, (__half*)pH);
        }
        cudaEventRecord(evR[c], s2);
    }
    cudaStreamWaitEvent(0, evR[NCHUNK - 1], 0);

    // 5) Y = H @ W^T + c
    gemm_tn2<<<dim3(SB / 128, (VOCABN + 63) / 64), 256, N_SMEM>>>(
        (const __half*)pH, (const __half*)pWh, (const __half*)pWl,
        cv, y_out, VOCABN, HDIM);
}

// round 17
// speedup vs baseline: 1.7541x; 1.0118x over previous
#include <cuda_runtime.h>
#include <cuda_fp16.h>

#define SEQ    256
#define BATCH  32
#define IDIM   256
#define HDIM   512
#define VOCABN 10000
#define SB     (SEQ*BATCH)      /* 8192 */
#define CHUNK  32
#define NCHUNK (SEQ/CHUNK)      /* 8 */
#define MC     (CHUNK*BATCH)    /* 1024 */

#define KSTR   72               /* padded smem k-stride (fp16 elems), 144B */
#define A_EL   (128*KSTR)       /* 9216 */
#define B_EL   (64*KSTR)        /* 4608 */

/* gemm_tn (P/Y): m-side single + weight hi(+lo) */
#define N_STAGE_EL (A_EL + 2*B_EL)      /* 18432 */
#define N_SMEM     (2*N_STAGE_EL*2)     /* 73728 */

/* gemm_T2: m-side single + A single (1-pass) */
#define T_STAGE_EL (A_EL + B_EL)        /* 13824 */
#define T_SMEM     (2*T_STAGE_EL*2)     /* 55296 */

typedef unsigned int u32;

// ---------------- static device scratch ----------------
__device__ __half  g_T0[(size_t)MC * HDIM * HDIM];     // 512 MB, parity 0
__device__ __half  g_T1[(size_t)MC * HDIM * HDIM];     // 512 MB, parity 1
__device__ __half  g_Ah[(size_t)HDIM * IDIM * HDIM];   // A (single fp16)
__device__ __half  g_Wh[(size_t)VOCABN * HDIM];        // W (single fp16)
__device__ __half  g_Uh[(size_t)HDIM * IDIM];
__device__ __half  g_Ul[(size_t)HDIM * IDIM];
__device__ __half  g_X [(size_t)SB * IDIM];            // X single fp16
__device__ __half  g_H [(size_t)SB * HDIM];            // H single fp16
__device__ float   g_P [(size_t)SB * HDIM];

// ---------------- ptx helpers ----------------
__device__ __forceinline__ void mmaf16(float c[4], const u32 a[4], const u32 b[2]) {
    asm volatile(
        "mma.sync.aligned.m16n8k16.row.col.f32.f16.f16.f32 "
        "{%0,%1,%2,%3}, {%4,%5,%6,%7}, {%8,%9}, {%0,%1,%2,%3};\n"
        : "+f"(c[0]), "+f"(c[1]), "+f"(c[2]), "+f"(c[3])
        : "r"(a[0]), "r"(a[1]), "r"(a[2]), "r"(a[3]), "r"(b[0]), "r"(b[1]));
}
__device__ __forceinline__ u32 smem_u32(const void* p) {
    return (u32)__cvta_generic_to_shared(p);
}
__device__ __forceinline__ void cpa16(u32 dst, const void* src, int sz) {
    asm volatile("cp.async.cg.shared.global [%0], [%1], 16, %2;\n"
                 :: "r"(dst), "l"(src), "r"(sz));
}
__device__ __forceinline__ void cpcommit() { asm volatile("cp.async.commit_group;\n"); }
template<int N> __device__ __forceinline__ void cpwait() {
    asm volatile("cp.async.wait_group %0;\n" :: "n"(N));
}
__device__ __forceinline__ void ldsm4(u32& r0, u32& r1, u32& r2, u32& r3, u32 a) {
    asm volatile("ldmatrix.sync.aligned.m8n8.x4.shared.b16 {%0,%1,%2,%3}, [%4];\n"
                 : "=r"(r0), "=r"(r1), "=r"(r2), "=r"(r3) : "r"(a));
}
__device__ __forceinline__ void ldsm4t(u32& r0, u32& r1, u32& r2, u32& r3, u32 a) {
    asm volatile("ldmatrix.sync.aligned.m8n8.x4.trans.shared.b16 {%0,%1,%2,%3}, [%4];\n"
                 : "=r"(r0), "=r"(r1), "=r"(r2), "=r"(r3) : "r"(a));
}

// ---------------- convert / split / embed ----------------
struct __align__(8) Hf4 { __half a, b, c, d; };

__global__ void cvt_kernel(const float4* __restrict__ src, Hf4* __restrict__ dst, int n4) {
    int i = blockIdx.x * blockDim.x + threadIdx.x;
    if (i >= n4) return;
    float4 v = src[i];
    Hf4 h;
    h.a = __float2half_rn(v.x); h.b = __float2half_rn(v.y);
    h.c = __float2half_rn(v.z); h.d = __float2half_rn(v.w);
    dst[i] = h;
}

__global__ void split_kernel(const float4* __restrict__ src,
                             Hf4* __restrict__ hi, Hf4* __restrict__ lo, int n4) {
    int i = blockIdx.x * blockDim.x + threadIdx.x;
    if (i >= n4) return;
    float4 v = src[i];
    Hf4 h, l;
    h.a = __float2half_rn(v.x); l.a = __float2half_rn(v.x - __half2float(h.a));
    h.b = __float2half_rn(v.y); l.b = __float2half_rn(v.y - __half2float(h.b));
    h.c = __float2half_rn(v.z); l.c = __float2half_rn(v.z - __half2float(h.c));
    h.d = __float2half_rn(v.w); l.d = __float2half_rn(v.w - __half2float(h.d));
    hi[i] = h; lo[i] = l;
}

__global__ void embed_kernel(const int* __restrict__ tok, const float* __restrict__ E,
                             __half* __restrict__ X) {
    int sb = blockIdx.x;
    int i  = threadIdx.x;
    X[(size_t)sb * IDIM + i] = __float2half_rn(E[(size_t)tok[sb] * IDIM + i]);
}

// =======================================================================
// T GEMM (1-pass fp16, fp16 output): T[mloc][j][n] = sum_i X*A + V
// BM=128 BN=64 BK=64, 2-stage cp.async, ldmatrix(.trans).
// grid (MC/128, HDIM/64, HDIM)
// =======================================================================
__global__ __launch_bounds__(256) void gemm_T2(
    const float* __restrict__ Vw, __half* __restrict__ T, int chunk)
{
    extern __shared__ __half sm[];
    const int tid = threadIdx.x, lane = tid & 31, w = tid >> 5;
    const int grp = lane >> 2, qp2 = (lane & 3) * 2;
    const int wm0 = (w & 3) * 32, wn0 = (w >> 2) * 32;
    const int j = blockIdx.z, mBase = blockIdx.x * 128, nBase = blockIdx.y * 64;
    const int mG = chunk * MC + mBase;

    float acc[2][4][4];
#pragma unroll
    for (int a = 0; a < 2; a++)
#pragma unroll
        for (int b = 0; b < 4; b++)
#pragma unroll
            for (int c = 0; c < 4; c++) acc[a][b][c] = 0.f;

#define PREFETCH_T(kc_) do {                                                   \
    int st_ = (kc_) & 1;                                                       \
    int kB_ = (kc_) * 64;                                                      \
    __half* Xs_ = sm + st_ * T_STAGE_EL;                                       \
    __half* Bh_ = Xs_ + A_EL;                                                  \
    _Pragma("unroll")                                                          \
    for (int q = 0; q < 4; q++) {                                              \
        int id = q * 256 + tid;                                                \
        int row = id >> 3, ks = (id & 7) * 8;                                  \
        size_t g = (size_t)(mG + row) * IDIM + kB_ + ks;                       \
        cpa16(smem_u32(Xs_ + row * KSTR + ks), g_X + g, 16);                   \
    }                                                                          \
    _Pragma("unroll")                                                          \
    for (int q = 0; q < 2; q++) {                                              \
        int id = q * 256 + tid;                                                \
        int kr = id >> 3, ns = (id & 7) * 8;                                   \
        size_t g = ((size_t)j * IDIM + kB_ + kr) * HDIM + nBase + ns;          \
        cpa16(smem_u32(Bh_ + kr * KSTR + ns), g_Ah + g, 16);                   \
    } } while (0)

    PREFETCH_T(0); cpcommit();

    const int r8 = lane & 7, kh = (lane >> 3) & 1, nh = lane >> 4;

    for (int kc = 0; kc < 4; kc++) {
        if (kc < 3) { PREFETCH_T(kc + 1); cpcommit(); cpwait<1>(); }
        else        { cpwait<0>(); }
        __syncthreads();
        int st = kc & 1;
        __half* Xs_ = sm + st * T_STAGE_EL;
        u32 aAd  = smem_u32(Xs_ + (wm0 + (lane & 15)) * KSTR + (lane >> 4) * 8);
        u32 bAdH = smem_u32(Xs_ + A_EL + (kh * 8 + r8) * KSTR + wn0 + nh * 8);
#pragma unroll
        for (int ks = 0; ks < 4; ks++) {
            u32 aF[2][4], bH[4][2];
            ldsm4(aF[0][0], aF[0][1], aF[0][2], aF[0][3], aAd + ks * 32);
            ldsm4(aF[1][0], aF[1][1], aF[1][2], aF[1][3], aAd + 2304 + ks * 32);
            ldsm4t(bH[0][0], bH[0][1], bH[1][0], bH[1][1], bAdH + ks * 2304);
            ldsm4t(bH[2][0], bH[2][1], bH[3][0], bH[3][1], bAdH + 32 + ks * 2304);
#pragma unroll
            for (int mt = 0; mt < 2; mt++)
#pragma unroll
                for (int nt = 0; nt < 4; nt++)
                    mmaf16(acc[mt][nt], aF[mt], bH[nt]);
        }
        __syncthreads();
    }
#undef PREFETCH_T

#pragma unroll
    for (int mt = 0; mt < 2; mt++)
#pragma unroll
        for (int nt = 0; nt < 4; nt++) {
            int r  = mBase + wm0 + mt * 16 + grp;
            int cc = nBase + wn0 + nt * 8 + qp2;
            float2 v2 = *(const float2*)&Vw[(size_t)j * HDIM + cc];
            size_t base = ((size_t)r * HDIM + j) * HDIM + cc;
            *(__half2*)&T[base] =
                __floats2half2_rn(acc[mt][nt][0] + v2.x, acc[mt][nt][1] + v2.y);
            *(__half2*)&T[base + (size_t)8 * HDIM * HDIM] =
                __floats2half2_rn(acc[mt][nt][2] + v2.x, acc[mt][nt][3] + v2.y);
        }
}

// =======================================================================
// TN GEMM (PASSES = 1 or 2): C[m][n] = sum_k A[m][k]*B[n][k] + bias[n]
// =======================================================================
template<int PASSES>
__global__ __launch_bounds__(256) void gemm_tn(
    const __half* __restrict__ Ap,
    const __half* __restrict__ Bhp, const __half* __restrict__ Blp,
    const float* __restrict__ bias, float* __restrict__ C, int N, int K)
{
    extern __shared__ __half sm[];
    const int tid = threadIdx.x, lane = tid & 31, w = tid >> 5;
    const int grp = lane >> 2, qp2 = (lane & 3) * 2;
    const int wm0 = (w & 3) * 32, wn0 = (w >> 2) * 32;
    const int mBase = blockIdx.x * 128, nBase = blockIdx.y * 64;
    const int KC = K >> 6;

    float acc[2][4][4];
#pragma unroll
    for (int a = 0; a < 2; a++)
#pragma unroll
        for (int b = 0; b < 4; b++)
#pragma unroll
            for (int c = 0; c < 4; c++) acc[a][b][c] = 0.f;

#define PREFETCH_N(kc_) do {                                                   \
    int st_ = (kc_) & 1;                                                       \
    int kB_ = (kc_) * 64;                                                      \
    __half* As_ = sm + st_ * N_STAGE_EL;                                       \
    __half* Bh_ = As_ + A_EL;                                                  \
    __half* Bl_ = Bh_ + B_EL;                                                  \
    _Pragma("unroll")                                                          \
    for (int q = 0; q < 4; q++) {                                              \
        int id = q * 256 + tid;                                                \
        int row = id >> 3, ks = (id & 7) * 8;                                  \
        size_t g = (size_t)(mBase + row) * K + kB_ + ks;                       \
        cpa16(smem_u32(As_ + row * KSTR + ks), Ap + g, 16);                    \
    }                                                                          \
    _Pragma("unroll")                                                          \
    for (int q = 0; q < 2; q++) {                                              \
        int id = q * 256 + tid;                                                \
        int nr = id >> 3, ks = (id & 7) * 8;                                   \
        int gn = nBase + nr;                                                   \
        int ok = gn < N;                                                       \
        int gc = ok ? gn : (N - 1);                                            \
        size_t g = (size_t)gc * K + kB_ + ks;                                  \
        cpa16(smem_u32(Bh_ + nr * KSTR + ks), Bhp + g, ok ? 16 : 0);           \
        if (PASSES == 2)                                                       \
            cpa16(smem_u32(Bl_ + nr * KSTR + ks), Blp + g, ok ? 16 : 0);       \
    } } while (0)

    PREFETCH_N(0); cpcommit();

    const int r8 = lane & 7, kh = (lane >> 3) & 1, nh = lane >> 4;

    for (int kc = 0; kc < KC; kc++) {
        if (kc < KC - 1) { PREFETCH_N(kc + 1); cpcommit(); cpwait<1>(); }
        else             { cpwait<0>(); }
        __syncthreads();
        int st = kc & 1;
        __half* As_ = sm + st * N_STAGE_EL;
        u32 aAd  = smem_u32(As_ + (wm0 + (lane & 15)) * KSTR + (lane >> 4) * 8);
        u32 bAdH = smem_u32(As_ + A_EL + (wn0 + nh * 8 + r8) * KSTR + kh * 8);
        u32 bAdL = bAdH + B_EL * 2;
#pragma unroll
        for (int ks = 0; ks < 4; ks++) {
            u32 aF[2][4], bH[4][2], bL[4][2];
            ldsm4(aF[0][0], aF[0][1], aF[0][2], aF[0][3], aAd + ks * 32);
            ldsm4(aF[1][0], aF[1][1], aF[1][2], aF[1][3], aAd + 2304 + ks * 32);
            ldsm4(bH[0][0], bH[0][1], bH[1][0], bH[1][1], bAdH + ks * 32);
            ldsm4(bH[2][0], bH[2][1], bH[3][0], bH[3][1], bAdH + 2304 + ks * 32);
            if (PASSES == 2) {
                ldsm4(bL[0][0], bL[0][1], bL[1][0], bL[1][1], bAdL + ks * 32);
                ldsm4(bL[2][0], bL[2][1], bL[3][0], bL[3][1], bAdL + 2304 + ks * 32);
            }
#pragma unroll
            for (int mt = 0; mt < 2; mt++)
#pragma unroll
                for (int nt = 0; nt < 4; nt++)
                    mmaf16(acc[mt][nt], aF[mt], bH[nt]);
            if (PASSES == 2) {
#pragma unroll
                for (int mt = 0; mt < 2; mt++)
#pragma unroll
                    for (int nt = 0; nt < 4; nt++)
                        mmaf16(acc[mt][nt], aF[mt], bL[nt]);
            }
        }
        __syncthreads();
    }
#undef PREFETCH_N

#pragma unroll
    for (int mt = 0; mt < 2; mt++)
#pragma unroll
        for (int nt = 0; nt < 4; nt++) {
            int r0 = mBase + wm0 + mt * 16 + grp;
            int cc = nBase + wn0 + nt * 8 + qp2;
            if (cc < N) {
                float b0 = bias[cc], b1 = bias[cc + 1];
                *(float2*)&C[(size_t)r0 * N + cc] =
                    make_float2(acc[mt][nt][0] + b0, acc[mt][nt][1] + b1);
                *(float2*)&C[(size_t)(r0 + 8) * N + cc] =
                    make_float2(acc[mt][nt][2] + b0, acc[mt][nt][3] + b1);
            }
        }
}

// ------------- recurrence (per-step, 2048 x 128-thread blocks, fp16 T) ----
// Small blocks so they co-reside with gemm_T CTAs on the high-prio stream.
__global__ __launch_bounds__(128) void recur_step(
    const __half* __restrict__ T, int sLocal, int s,
    float* __restrict__ Hfull, __half* __restrict__ Hh)
{
    const int tid = threadIdx.x, lane = tid & 31, w = tid >> 5;  // w: 0..3
    const int b = blockIdx.x & 31, jt = blockIdx.x >> 5;          // jt: 0..63
    __shared__ float hs[HDIM];
    if (s > 0) {
        const float* hp = Hfull + ((size_t)(s - 1) * BATCH + b) * HDIM;
        for (int k = tid; k < HDIM; k += 128) hs[k] = hp[k];
    }
    __syncthreads();
    const int mloc = sLocal * BATCH + b;
    const int m    = s * BATCH + b;
#pragma unroll
    for (int jj = 0; jj < 2; jj++) {
        int j = jt * 8 + w * 2 + jj;
        float a = 0.f;
        if (s > 0) {
            const uint4* row = (const uint4*)(T + ((size_t)mloc * HDIM + j) * HDIM);
#pragma unroll
            for (int q = 0; q < 2; q++) {
                uint4 v = row[lane + q * 32];
                const __half2* h2 = (const __half2*)&v;
                int k = (lane + q * 32) * 8;
#pragma unroll
                for (int u = 0; u < 4; u++) {
                    float2 f = __half22float2(h2[u]);
                    a += f.x * hs[k + 2 * u] + f.y * hs[k + 2 * u + 1];
                }
            }
        }
#pragma unroll
        for (int off = 16; off; off >>= 1) a += __shfl_xor_sync(~0u, a, off);
        if (lane == 0) {
            float pre = a + g_P[(size_t)m * HDIM + j];
            float h = pre > 0.f ? pre : 0.f;
            Hfull[(size_t)m * HDIM + j] = h;
            Hh[(size_t)m * HDIM + j] = __float2half_rn(h);
        }
    }
}

// ---------------- host ----------------
extern "C" void kernel_launch(void* const* d_in, const int* in_sizes, int n_in,
                              void* d_out, int out_size) {
    const int*   tok = (const int*)  d_in[0];
    const float* E   = (const float*)d_in[1];
    const float* A   = (const float*)d_in[2];
    const float* U   = (const float*)d_in[3];
    const float* V   = (const float*)d_in[4];
    const float* bv  = (const float*)d_in[5];
    const float* W   = (const float*)d_in[6];
    const float* cv  = (const float*)d_in[7];

    float* y_out = (float*)d_out;                              // [SB][VOCAB]
    float* h_out = (float*)d_out + (size_t)SB * VOCABN;        // [SB][H]

    void *pT0, *pT1, *pAh, *pWh, *pUh, *pUl, *pX, *pH, *pP;
    cudaGetSymbolAddress(&pT0, g_T0); cudaGetSymbolAddress(&pT1, g_T1);
    cudaGetSymbolAddress(&pAh, g_Ah);
    cudaGetSymbolAddress(&pWh, g_Wh);
    cudaGetSymbolAddress(&pUh, g_Uh); cudaGetSymbolAddress(&pUl, g_Ul);
    cudaGetSymbolAddress(&pX,  g_X);  cudaGetSymbolAddress(&pH,  g_H);
    cudaGetSymbolAddress(&pP,  g_P);
    __half* bufT[2] = { (__half*)pT0, (__half*)pT1 };

    cudaFuncSetAttribute(gemm_T2, cudaFuncAttributeMaxDynamicSharedMemorySize, T_SMEM);
    cudaFuncSetAttribute(gemm_tn<1>, cudaFuncAttributeMaxDynamicSharedMemorySize, N_SMEM);
    cudaFuncSetAttribute(gemm_tn<2>, cudaFuncAttributeMaxDynamicSharedMemorySize, N_SMEM);

    // high-priority side stream so recur CTAs preempt queued gemm_T CTAs
    int prLow, prHigh;
    cudaDeviceGetStreamPriorityRange(&prLow, &prHigh);
    cudaStream_t s2;
    cudaStreamCreateWithPriority(&s2, cudaStreamNonBlocking, prHigh);
    cudaEvent_t evG[NCHUNK], evR[NCHUNK];
    for (int c = 0; c < NCHUNK; c++) {
        cudaEventCreateWithFlags(&evG[c], cudaEventDisableTiming);
        cudaEventCreateWithFlags(&evR[c], cudaEventDisableTiming);
    }

    // 1) A, W -> single fp16; U -> fp16 hi/lo split
    {
        int n4 = (HDIM * IDIM * HDIM) / 4;
        cvt_kernel<<<(n4 + 255) / 256, 256>>>((const float4*)A, (Hf4*)pAh, n4);
        n4 = (VOCABN * HDIM) / 4;
        cvt_kernel<<<(n4 + 255) / 256, 256>>>((const float4*)W, (Hf4*)pWh, n4);
        n4 = (HDIM * IDIM) / 4;
        split_kernel<<<(n4 + 255) / 256, 256>>>((const float4*)U, (Hf4*)pUh, (Hf4*)pUl, n4);
    }
    // 2) embedding gather (single fp16)
    embed_kernel<<<SB, IDIM>>>(tok, E, (__half*)pX);

    // 3) P = X @ U^T + b   (2-pass for precision into the recurrence)
    gemm_tn<2><<<dim3(SB / 128, HDIM / 64), 256, N_SMEM>>>(
        (const __half*)pX, (const __half*)pUh, (const __half*)pUl,
        bv, (float*)pP, HDIM, IDIM);

    // 4) pipeline: gemm_T(c) on stream 0; per-step recur chain on s2 (high prio).
    //    WAR guard: gemm_T(c) (writing bufT[c&1]) waits recur(c-2).
    for (int c = 0; c < NCHUNK; c++) {
        if (c >= 2) cudaStreamWaitEvent(0, evR[c - 2], 0);
        gemm_T2<<<dim3(MC / 128, HDIM / 64, HDIM), 256, T_SMEM>>>(V, bufT[c & 1], c);
        cudaEventRecord(evG[c], 0);
        cudaStreamWaitEvent(s2, evG[c], 0);
        for (int t = 0; t < CHUNK; t++) {
            int s = c * CHUNK + t;
            recur_step<<<2048, 128, 0, s2>>>(bufT[c & 1], t, s, h_out, (__half*)pH);
        }
        cudaEventRecord(evR[c], s2);
    }
    cudaStreamWaitEvent(0, evR[NCHUNK - 1], 0);

    // 5) Y = H @ W^T + c   (1-pass, W single fp16)
    gemm_tn<1><<<dim3(SB / 128, (VOCABN + 63) / 64), 256, N_SMEM>>>(
        (const __half*)pH, (const __half*)pWh, (const __half*)pWh,
        cv, y_out, VOCABN, HDIM);
}